// round 13
// baseline (speedup 1.0000x reference)
#include <cuda_runtime.h>
#include <cuda_bf16.h>
#include <cmath>
#include <cstdint>

#define B_ 4
#define T_ 1024
#define D_ 768
#define N_ 7
#define BT_ (B_ * T_)
#define ND_ (N_ * D_)
#define DD_ (D_ * D_)

// ---------------- scratch (device globals; no allocation allowed) ----------------
__device__ float g_h[BT_ * D_];                        // LN(x)  (fp32 master)
__device__ float g_Z[BT_ * D_];                        // h + seq (fp32 master)
__device__ float g_S[(size_t)N_ * B_ * T_ * T_];       // fp32 scores
__device__ float g_E[(size_t)N_ * BT_ * D_];           // attention outputs (fp32)
__device__ float g_par[BT_ * D_];                      // merged parallel branch

__device__ __align__(16) __nv_bfloat16 g_hb[BT_ * D_];             // bf16 h
__device__ __align__(16) __nv_bfloat16 g_Zb[BT_ * D_];             // bf16 Z
__device__ __align__(16) __nv_bfloat16 g_hT[(size_t)B_ * D_ * T_]; // h^T per batch
__device__ __align__(16) __nv_bfloat16 g_ZT[(size_t)B_ * D_ * T_]; // Z^T per batch
__device__ __align__(16) __nv_bfloat16 g_WT[(size_t)2 * N_ * DD_]; // [Wq^T(0..6) | Wk^T(0..6)]
__device__ __align__(16) __nv_bfloat16 g_mWb[(size_t)D_ * ND_];    // merge_W bf16
__device__ __align__(16) __nv_bfloat16 g_qkb[(size_t)2 * N_ * BT_ * D_]; // [q(7) | k(7)]
__device__ __align__(16) __nv_bfloat16 g_Pb[(size_t)N_ * B_ * T_ * T_];  // probs bf16
__device__ __align__(16) __nv_bfloat16 g_db[(size_t)BT_ * ND_];          // deltas bf16

// ---------------- reduction helpers (256 threads) ----------------
__device__ __forceinline__ float blockReduceSum(float v, float* sh) {
    int t = threadIdx.x;
    sh[t] = v; __syncthreads();
    #pragma unroll
    for (int s = 128; s > 0; s >>= 1) { if (t < s) sh[t] += sh[t + s]; __syncthreads(); }
    float r = sh[0]; __syncthreads(); return r;
}
__device__ __forceinline__ float blockReduceMax(float v, float* sh) {
    int t = threadIdx.x;
    sh[t] = v; __syncthreads();
    #pragma unroll
    for (int s = 128; s > 0; s >>= 1) { if (t < s) sh[t] = fmaxf(sh[t], sh[t + s]); __syncthreads(); }
    float r = sh[0]; __syncthreads(); return r;
}

__device__ __forceinline__ uint32_t packbf(float lo, float hi) {
    __nv_bfloat162 h = __floats2bfloat162_rn(lo, hi);
    return *(uint32_t*)&h;
}

__device__ __forceinline__ void mma_bf16(float* c, uint32_t a0, uint32_t a1,
                                         uint32_t a2, uint32_t a3,
                                         uint32_t b0, uint32_t b1) {
    asm volatile(
        "mma.sync.aligned.m16n8k16.row.col.f32.bf16.bf16.f32 "
        "{%0,%1,%2,%3}, {%4,%5,%6,%7}, {%8,%9}, {%0,%1,%2,%3};"
        : "+f"(c[0]), "+f"(c[1]), "+f"(c[2]), "+f"(c[3])
        : "r"(a0), "r"(a1), "r"(a2), "r"(a3), "r"(b0), "r"(b1));
}

__device__ __forceinline__ void ldsm_x4(uint32_t& r0, uint32_t& r1, uint32_t& r2,
                                        uint32_t& r3, uint32_t addr) {
    asm volatile("ldmatrix.sync.aligned.m8n8.x4.shared.b16 {%0,%1,%2,%3}, [%4];"
                 : "=r"(r0), "=r"(r1), "=r"(r2), "=r"(r3) : "r"(addr));
}

#define CP_ASYNC16(dst, src) \
    asm volatile("cp.async.cg.shared.global [%0], [%1], 16;" :: "r"(dst), "l"(src))
#define CP_COMMIT asm volatile("cp.async.commit_group;" ::: "memory")
#define CP_WAIT0  asm volatile("cp.async.wait_group 0;" ::: "memory")
#define CP_WAIT1  asm volatile("cp.async.wait_group 1;" ::: "memory")

// ---------------- bf16 tensor-core GEMM: C = alpha * A @ B^T ----------------
// A: M x K row-major bf16.  B: N x K row-major bf16 (used transposed).
// 128x128 block tile, BK=64, 256 threads (8 warps 4x2), warp tile 32x64.
// 3-stage cp.async ring (wait_group 1 => two tiles of prefetch in flight),
// one __syncthreads per 64-wide K-tile; ldmatrix.x4 fragment loads.
// Smem word tiles [128][36] (32 data + 4 pad): STS.128 and LDSM both
// conflict-free ((36g + t) mod 32 distinct within each 8-row matrix).
// CAUSAL: grid (x=s-tile, y=t-tile); blocks strictly above diagonal skipped.
// Batched over z: A/C advance by sA/sC; B advances by (z % zmodB)*sB.
#define SW 36
#define TILE_W (128 * SW)
#define STG_B (2 * TILE_W * 4)
#define NSTG 3
#define SMEM_GEMM (NSTG * STG_B)
template <bool CAUSAL, bool OUTBF>
__global__ __launch_bounds__(256)
void bgemm_kernel(const __nv_bfloat16* __restrict__ A, const __nv_bfloat16* __restrict__ Bm,
                  void* __restrict__ Cv, int K, int lda, int ldb, int ldc,
                  long sA, long sB, long sC, int zmodB, float alpha) {
    if (CAUSAL && (int)blockIdx.y < (int)blockIdx.x) return;
    A  += (size_t)blockIdx.z * sA;
    Bm += (size_t)(blockIdx.z % zmodB) * sB;

    extern __shared__ uint32_t sm4[];

    int tid = threadIdx.x;
    int lane = tid & 31, wid = tid >> 5;
    int gID = lane >> 2, tig = lane & 3;
    int warp_m = (wid & 3) * 32, warp_n = (wid >> 2) * 64;
    int row0 = blockIdx.y * 128, col0 = blockIdx.x * 128;

    uint32_t sbase = (uint32_t)__cvta_generic_to_shared(sm4);

    // loader: row lr, k-half lh (32 bf16 = 16 words each); 4x16B per operand/tile
    int lr = tid >> 1, lh = tid & 1;
    const __nv_bfloat16* Ag = A + (size_t)(row0 + lr) * lda + lh * 32;
    const __nv_bfloat16* Bg = Bm + (size_t)(col0 + lr) * ldb + lh * 32;
    uint32_t adst = sbase + (uint32_t)(lr * SW + lh * 16) * 4;
    uint32_t bdst = adst + TILE_W * 4;

    // ldmatrix lane addressing
    int mat = lane >> 3, mr = lane & 7;
    uint32_t aoff = sbase + (uint32_t)((warp_m + (mat & 1) * 8 + mr) * SW) * 4 + (mat >> 1) * 16;
    uint32_t boff = sbase + TILE_W * 4 +
                    (uint32_t)((warp_n + (mat >> 1) * 8 + mr) * SW) * 4 + (mat & 1) * 16;

    float acc[2][8][4] = {};

    const int NT = K >> 6;

    // prefetch tiles 0 and 1
    #pragma unroll
    for (int p = 0; p < 2; p++) {
        if (p < NT) {
            uint32_t so = (uint32_t)p * STG_B;
            int k0 = p << 6;
            #pragma unroll
            for (int c = 0; c < 4; c++) {
                CP_ASYNC16(adst + so + c * 16, Ag + k0 + c * 8);
                CP_ASYNC16(bdst + so + c * 16, Bg + k0 + c * 8);
            }
            CP_COMMIT;
        }
    }

    for (int t = 0; t < NT; t++) {
        if (t + 1 < NT) { CP_WAIT1; } else { CP_WAIT0; }
        __syncthreads();   // tile t visible; all warps done with tile t-1's slot

        if (t + 2 < NT) {
            uint32_t so = (uint32_t)((t + 2) % NSTG) * STG_B;
            int k0 = (t + 2) << 6;
            #pragma unroll
            for (int c = 0; c < 4; c++) {
                CP_ASYNC16(adst + so + c * 16, Ag + k0 + c * 8);
                CP_ASYNC16(bdst + so + c * 16, Bg + k0 + c * 8);
            }
            CP_COMMIT;
        }

        uint32_t so = (uint32_t)(t % NSTG) * STG_B;
        #pragma unroll
        for (int s = 0; s < 4; s++) {
            uint32_t a[2][4];
            #pragma unroll
            for (int mt = 0; mt < 2; mt++)
                ldsm_x4(a[mt][0], a[mt][1], a[mt][2], a[mt][3],
                        aoff + so + s * 32 + mt * (16 * SW * 4));
            uint32_t bf[8][2];
            #pragma unroll
            for (int p = 0; p < 4; p++)
                ldsm_x4(bf[2 * p][0], bf[2 * p][1], bf[2 * p + 1][0], bf[2 * p + 1][1],
                        boff + so + s * 32 + p * (16 * SW * 4));
            #pragma unroll
            for (int mt = 0; mt < 2; mt++)
                #pragma unroll
                for (int nt = 0; nt < 8; nt++)
                    mma_bf16(acc[mt][nt], a[mt][0], a[mt][1], a[mt][2], a[mt][3],
                             bf[nt][0], bf[nt][1]);
        }
    }

    if (OUTBF) {
        __nv_bfloat16* C = (__nv_bfloat16*)Cv + (size_t)blockIdx.z * sC;
        #pragma unroll
        for (int mt = 0; mt < 2; mt++) {
            int rg = row0 + warp_m + mt * 16 + gID;
            #pragma unroll
            for (int nt = 0; nt < 8; nt++) {
                int cg = col0 + warp_n + nt * 8 + 2 * tig;
                *(uint32_t*)(C + (size_t)rg * ldc + cg) =
                    packbf(acc[mt][nt][0] * alpha, acc[mt][nt][1] * alpha);
                *(uint32_t*)(C + (size_t)(rg + 8) * ldc + cg) =
                    packbf(acc[mt][nt][2] * alpha, acc[mt][nt][3] * alpha);
            }
        }
    } else {
        float* C = (float*)Cv + (size_t)blockIdx.z * sC;
        #pragma unroll
        for (int mt = 0; mt < 2; mt++) {
            int rg = row0 + warp_m + mt * 16 + gID;
            #pragma unroll
            for (int nt = 0; nt < 8; nt++) {
                int cg = col0 + warp_n + nt * 8 + 2 * tig;
                *(float2*)(C + (size_t)rg * ldc + cg) =
                    make_float2(acc[mt][nt][0] * alpha, acc[mt][nt][1] * alpha);
                *(float2*)(C + (size_t)(rg + 8) * ldc + cg) =
                    make_float2(acc[mt][nt][2] * alpha, acc[mt][nt][3] * alpha);
            }
        }
    }
}

// ---------------- transposes / conversions ----------------
__global__ void transpose_f2b_kernel(const float* __restrict__ in, __nv_bfloat16* __restrict__ out,
                                     int R, int C, long sIn, long sOut) {
    __shared__ float tile[32][33];
    in  += (size_t)blockIdx.z * sIn;
    out += (size_t)blockIdx.z * sOut;
    int c0 = blockIdx.x * 32, r0 = blockIdx.y * 32;
    #pragma unroll
    for (int i = 0; i < 4; i++)
        tile[threadIdx.y + 8 * i][threadIdx.x] =
            in[(size_t)(r0 + threadIdx.y + 8 * i) * C + c0 + threadIdx.x];
    __syncthreads();
    #pragma unroll
    for (int i = 0; i < 4; i++)
        out[(size_t)(c0 + threadIdx.y + 8 * i) * R + r0 + threadIdx.x] =
            __float2bfloat16(tile[threadIdx.x][threadIdx.y + 8 * i]);
}

__global__ void transpose_b2b_kernel(const __nv_bfloat16* __restrict__ in,
                                     __nv_bfloat16* __restrict__ out,
                                     int R, int C, long sIn, long sOut) {
    __shared__ __nv_bfloat16 tile[32][33];
    in  += (size_t)blockIdx.z * sIn;
    out += (size_t)blockIdx.z * sOut;
    int c0 = blockIdx.x * 32, r0 = blockIdx.y * 32;
    #pragma unroll
    for (int i = 0; i < 4; i++)
        tile[threadIdx.y + 8 * i][threadIdx.x] =
            in[(size_t)(r0 + threadIdx.y + 8 * i) * C + c0 + threadIdx.x];
    __syncthreads();
    #pragma unroll
    for (int i = 0; i < 4; i++)
        out[(size_t)(c0 + threadIdx.y + 8 * i) * R + r0 + threadIdx.x] =
            tile[threadIdx.x][threadIdx.y + 8 * i];
}

__global__ void convert_f2b_kernel(const float* __restrict__ in, __nv_bfloat16* __restrict__ out,
                                   int npairs) {
    int i = blockIdx.x * 256 + threadIdx.x;
    if (i < npairs)
        ((__nv_bfloat162*)out)[i] = __floats2bfloat162_rn(in[2 * i], in[2 * i + 1]);
}

// ---------------- LayerNorm (pre): h = LN(x); Z = h (+ bf16 mirrors) ----------------
__global__ void ln_pre_kernel(const float* __restrict__ x, const float* __restrict__ g,
                              const float* __restrict__ b, float* __restrict__ h,
                              float* __restrict__ Z, __nv_bfloat16* __restrict__ hb,
                              __nv_bfloat16* __restrict__ Zb) {
    __shared__ float sh[256];
    int row = blockIdx.x;
    const float* xr = x + (size_t)row * D_;
    float s = 0.f;
    for (int d = threadIdx.x; d < D_; d += 256) s += xr[d];
    float mean = blockReduceSum(s, sh) * (1.0f / D_);
    float v = 0.f;
    for (int d = threadIdx.x; d < D_; d += 256) { float t = xr[d] - mean; v += t * t; }
    float var = blockReduceSum(v, sh) * (1.0f / D_);
    float rstd = rsqrtf(var + 1e-5f);
    for (int d2 = threadIdx.x; d2 < D_ / 2; d2 += 256) {
        int d = 2 * d2;
        float v0 = (xr[d] - mean) * rstd * g[d] + b[d];
        float v1 = (xr[d + 1] - mean) * rstd * g[d + 1] + b[d + 1];
        size_t off = (size_t)row * D_ + d;
        h[off] = v0; h[off + 1] = v1;
        Z[off] = v0; Z[off + 1] = v1;
        __nv_bfloat162 pv = __floats2bfloat162_rn(v0, v1);
        ((__nv_bfloat162*)(hb + off))[0] = pv;
        ((__nv_bfloat162*)(Zb + off))[0] = pv;
    }
}

// ---------------- causal softmax: fp32 scores -> bf16 probs (zero-fill s>t) ----------------
__global__ void softmax_kernel(const float* __restrict__ S, __nv_bfloat16* __restrict__ P) {
    __shared__ float sh[256];
    int row = blockIdx.x;
    int t = row & (T_ - 1);
    const float* r = S + (size_t)row * T_;
    __nv_bfloat16* p = P + (size_t)row * T_;
    float m = -1e30f;
    for (int s = threadIdx.x; s <= t; s += 256) m = fmaxf(m, r[s]);
    m = blockReduceMax(m, sh);
    float sum = 0.f;
    for (int s = threadIdx.x; s <= t; s += 256) sum += __expf(r[s] - m);
    sum = blockReduceSum(sum, sh);
    float inv = 1.f / sum;
    for (int s2 = threadIdx.x; s2 < T_ / 2; s2 += 256) {
        int s = 2 * s2;
        float v0 = (s <= t) ? __expf(r[s] - m) * inv : 0.f;
        float v1 = (s + 1 <= t) ? __expf(r[s + 1] - m) * inv : 0.f;
        ((__nv_bfloat162*)p)[s2] = __floats2bfloat162_rn(v0, v1);
    }
}

// ---------------- parallel-branch epilogue: bf16 delta into concat buffer ----------------
__global__ void finish_par_kernel(const float* __restrict__ h, const float* __restrict__ Eall,
                                  __nv_bfloat16* __restrict__ del, const float* __restrict__ gw,
                                  const float* __restrict__ gb, const float* __restrict__ sp) {
    __shared__ float sh[256];
    int row = blockIdx.x, ci = blockIdx.y;
    const float* zr = h + (size_t)row * D_;
    const float* er = Eall + ((size_t)ci * BT_ + row) * D_;
    float dot = 0.f;
    for (int d = threadIdx.x; d < D_; d += 256) dot += zr[d] * gw[ci * D_ + d];
    dot = blockReduceSum(dot, sh);
    float gate = 1.f / (1.f + __expf(-(dot + gb[ci])));
    float f = log1pf(__expf(sp[ci])) * gate;   // curriculum mask == 1.0f exactly in fp32
    __nv_bfloat16* orow = del + (size_t)row * ND_ + (size_t)ci * D_;
    for (int d2 = threadIdx.x; d2 < D_ / 2; d2 += 256) {
        int d = 2 * d2;
        ((__nv_bfloat162*)orow)[d2] =
            __floats2bfloat162_rn(f * (er[d] - zr[d]), f * (er[d + 1] - zr[d + 1]));
    }
}

// ---------------- sequential-branch epilogue: Z += f*(E - Z) (+ bf16 mirror) ----------------
__global__ void finish_seq_kernel(float* __restrict__ Z, const float* __restrict__ E,
                                  const float* __restrict__ gw, const float* __restrict__ gb,
                                  const float* __restrict__ sp, int ci,
                                  __nv_bfloat16* __restrict__ Zb) {
    __shared__ float sh[256];
    int row = blockIdx.x;
    float* zr = Z + (size_t)row * D_;
    const float* er = E + (size_t)row * D_;
    float dot = 0.f;
    for (int d = threadIdx.x; d < D_; d += 256) dot += zr[d] * gw[ci * D_ + d];
    dot = blockReduceSum(dot, sh);
    float gate = 1.f / (1.f + __expf(-(dot + gb[ci])));
    float f = log1pf(__expf(sp[ci])) * gate;
    __nv_bfloat16* zb = Zb + (size_t)row * D_;
    for (int d2 = threadIdx.x; d2 < D_ / 2; d2 += 256) {
        int d = 2 * d2;
        float z0 = zr[d] + f * (er[d] - zr[d]);
        float z1 = zr[d + 1] + f * (er[d + 1] - zr[d + 1]);
        zr[d] = z0; zr[d + 1] = z1;
        ((__nv_bfloat162*)zb)[d2] = __floats2bfloat162_rn(z0, z1);
    }
}

// ---------------- combine: enr = (1-mg)*(Z-h) + mg*par; LN_post; out = x + rg*enr ----------------
__global__ void combine_kernel(const float* __restrict__ x, const float* __restrict__ h,
                               const float* __restrict__ Z, const float* __restrict__ par,
                               const float* __restrict__ g, const float* __restrict__ b,
                               const float* __restrict__ mode_logit,
                               const float* __restrict__ residual_gate,
                               float* __restrict__ out) {
    __shared__ float sh[256];
    __shared__ float e[D_];
    int row = blockIdx.x;
    float mg = 1.f / (1.f + __expf(-mode_logit[0]));
    float rg = residual_gate[0];
    size_t off = (size_t)row * D_;
    for (int d = threadIdx.x; d < D_; d += 256)
        e[d] = (1.f - mg) * (Z[off + d] - h[off + d]) + mg * par[off + d];
    __syncthreads();
    float s = 0.f;
    for (int d = threadIdx.x; d < D_; d += 256) s += e[d];
    float mean = blockReduceSum(s, sh) * (1.0f / D_);
    float v = 0.f;
    for (int d = threadIdx.x; d < D_; d += 256) { float t = e[d] - mean; v += t * t; }
    float var = blockReduceSum(v, sh) * (1.0f / D_);
    float rstd = rsqrtf(var + 1e-5f);
    for (int d = threadIdx.x; d < D_; d += 256)
        out[off + d] = x[off + d] + rg * ((e[d] - mean) * rstd * g[d] + b[d]);
}

// ---------------- host orchestration ----------------
extern "C" void kernel_launch(void* const* d_in, const int* in_sizes, int n_in,
                              void* d_out, int out_size) {
    (void)in_sizes; (void)n_in; (void)out_size;
    const float* x   = (const float*)d_in[0];
    const float* Wq  = (const float*)d_in[1];
    const float* Wk  = (const float*)d_in[2];
    const float* gw  = (const float*)d_in[3];
    const float* gb  = (const float*)d_in[4];
    const float* sp  = (const float*)d_in[5];
    const float* mW  = (const float*)d_in[6];
    const float* ml  = (const float*)d_in[7];
    const float* rg  = (const float*)d_in[8];
    const float* lpg = (const float*)d_in[9];
    const float* lpb = (const float*)d_in[10];
    const float* lqg = (const float*)d_in[11];
    const float* lqb = (const float*)d_in[12];
    float* out = (float*)d_out;

    float *h, *Z, *S, *E, *par;
    __nv_bfloat16 *hb, *Zb, *hT, *ZT, *WT, *mWb, *qkb, *Pb, *db;
    cudaGetSymbolAddress((void**)&h,   g_h);
    cudaGetSymbolAddress((void**)&Z,   g_Z);
    cudaGetSymbolAddress((void**)&S,   g_S);
    cudaGetSymbolAddress((void**)&E,   g_E);
    cudaGetSymbolAddress((void**)&par, g_par);
    cudaGetSymbolAddress((void**)&hb,  g_hb);
    cudaGetSymbolAddress((void**)&Zb,  g_Zb);
    cudaGetSymbolAddress((void**)&hT,  g_hT);
    cudaGetSymbolAddress((void**)&ZT,  g_ZT);
    cudaGetSymbolAddress((void**)&WT,  g_WT);
    cudaGetSymbolAddress((void**)&mWb, g_mWb);
    cudaGetSymbolAddress((void**)&qkb, g_qkb);
    cudaGetSymbolAddress((void**)&Pb,  g_Pb);
    cudaGetSymbolAddress((void**)&db,  g_db);

    __nv_bfloat16* kb = qkb + (size_t)N_ * BT_ * D_;

    cudaFuncSetAttribute(bgemm_kernel<false, true>,
                         cudaFuncAttributeMaxDynamicSharedMemorySize, SMEM_GEMM);
    cudaFuncSetAttribute(bgemm_kernel<true, false>,
                         cudaFuncAttributeMaxDynamicSharedMemorySize, SMEM_GEMM);
    cudaFuncSetAttribute(bgemm_kernel<false, false>,
                         cudaFuncAttributeMaxDynamicSharedMemorySize, SMEM_GEMM);

    const float alphaS = 1.0f / sqrtf((float)D_);
    const long TD  = (long)T_ * D_;
    const long TT  = (long)T_ * T_;
    const long DT  = (long)D_ * T_;
    const long BTD = (long)BT_ * D_;

    dim3 blk32(32, 8);

    // ---- prologue: LN + bf16 conversions/transposes ----
    ln_pre_kernel<<<BT_, 256>>>(x, lpg, lpb, h, Z, hb, Zb);
    transpose_f2b_kernel<<<dim3(D_ / 32, D_ / 32, N_), blk32>>>(Wq, WT, D_, D_, DD_, DD_);
    transpose_f2b_kernel<<<dim3(D_ / 32, D_ / 32, N_), blk32>>>(
        Wk, WT + (size_t)N_ * DD_, D_, D_, DD_, DD_);
    convert_f2b_kernel<<<((D_ * ND_ / 2) + 255) / 256, 256>>>(mW, mWb, D_ * ND_ / 2);
    transpose_b2b_kernel<<<dim3(D_ / 32, T_ / 32, B_), blk32>>>(hb, hT, T_, D_, TD, DT);
    transpose_b2b_kernel<<<dim3(D_ / 32, T_ / 32, B_), blk32>>>(Zb, ZT, T_, D_, TD, DT);

    // ===== parallel branch: all 7 chambers (q and k fused: z = 0..13) =====
    bgemm_kernel<false, true><<<dim3(6, 32, 2 * N_), 256, SMEM_GEMM>>>(
        hb, WT, qkb, D_, D_, D_, D_, 0, (long)DD_, BTD, 2 * N_, 1.f);
    bgemm_kernel<true, false><<<dim3(8, 8, N_ * B_), 256, SMEM_GEMM>>>(
        qkb, kb, S, D_, D_, D_, T_, TD, TD, TT, N_ * B_, alphaS);
    softmax_kernel<<<N_ * B_ * T_, 256>>>(S, Pb);
    bgemm_kernel<false, false><<<dim3(6, 8, N_ * B_), 256, SMEM_GEMM>>>(
        Pb, hT, E, T_, T_, T_, D_, TT, DT, TD, B_, 1.f);
    finish_par_kernel<<<dim3(BT_, N_), 256>>>(h, E, db, gw, gb, sp);
    bgemm_kernel<false, false><<<dim3(6, 32, 1), 256, SMEM_GEMM>>>(
        db, mWb, par, ND_, ND_, ND_, D_, 0, 0, 0, 1, 1.f);

    // ===== sequential branch: dependency chain =====
    for (int i = 0; i < N_; i++) {
        // q and k projections fused: z=0 -> Wq_i -> qkb, z=1 -> Wk_i -> kb
        bgemm_kernel<false, true><<<dim3(6, 32, 2), 256, SMEM_GEMM>>>(
            Zb, WT + (size_t)i * DD_, qkb, D_, D_, D_, D_,
            0, (long)N_ * DD_, (long)N_ * BTD, 2, 1.f);
        bgemm_kernel<true, false><<<dim3(8, 8, B_), 256, SMEM_GEMM>>>(
            qkb, kb, S, D_, D_, D_, T_, TD, TD, TT, B_, alphaS);
        softmax_kernel<<<BT_, 256>>>(S, Pb);
        bgemm_kernel<false, false><<<dim3(6, 8, B_), 256, SMEM_GEMM>>>(
            Pb, ZT, E, T_, T_, T_, D_, TT, DT, TD, B_, 1.f);
        finish_seq_kernel<<<BT_, 256>>>(Z, E, gw, gb, sp, i, Zb);
        transpose_b2b_kernel<<<dim3(D_ / 32, T_ / 32, B_), blk32>>>(Zb, ZT, T_, D_, TD, DT);
    }

    // ===== combine + LN_post + residual =====
    combine_kernel<<<BT_, 256>>>(x, h, Z, par, lqg, lqb, ml, rg, out);
}

// round 15
// speedup vs baseline: 1.1309x; 1.1309x over previous
#include <cuda_runtime.h>
#include <cuda_bf16.h>
#include <cmath>
#include <cstdint>

#define B_ 4
#define T_ 1024
#define D_ 768
#define N_ 7
#define BT_ (B_ * T_)
#define ND_ (N_ * D_)
#define DD_ (D_ * D_)

// ---------------- scratch (device globals; no allocation allowed) ----------------
__device__ float g_h[BT_ * D_];                        // LN(x)  (fp32 master)
__device__ float g_Z[BT_ * D_];                        // h + seq (fp32 master)
__device__ float g_S[(size_t)N_ * B_ * T_ * T_];       // fp32 scores
__device__ float g_E[(size_t)N_ * BT_ * D_];           // attention outputs (fp32)
__device__ float g_par[BT_ * D_];                      // merged parallel branch

__device__ __align__(16) __nv_bfloat16 g_hb[BT_ * D_];             // bf16 h
__device__ __align__(16) __nv_bfloat16 g_Zb[BT_ * D_];             // bf16 Z
__device__ __align__(16) __nv_bfloat16 g_hT[(size_t)B_ * D_ * T_]; // h^T per batch
__device__ __align__(16) __nv_bfloat16 g_ZT[(size_t)B_ * D_ * T_]; // Z^T per batch
__device__ __align__(16) __nv_bfloat16 g_WT[(size_t)2 * N_ * DD_]; // [Wq^T(0..6) | Wk^T(0..6)]
__device__ __align__(16) __nv_bfloat16 g_mWb[(size_t)D_ * ND_];    // merge_W bf16
__device__ __align__(16) __nv_bfloat16 g_qkb[(size_t)2 * N_ * BT_ * D_]; // [q(7) | k(7)]
__device__ __align__(16) __nv_bfloat16 g_Pb[(size_t)N_ * B_ * T_ * T_];  // probs bf16
__device__ __align__(16) __nv_bfloat16 g_db[(size_t)BT_ * ND_];          // deltas bf16

// ---------------- reduction helpers (256 threads) ----------------
__device__ __forceinline__ float blockReduceSum(float v, float* sh) {
    int t = threadIdx.x;
    sh[t] = v; __syncthreads();
    #pragma unroll
    for (int s = 128; s > 0; s >>= 1) { if (t < s) sh[t] += sh[t + s]; __syncthreads(); }
    float r = sh[0]; __syncthreads(); return r;
}
__device__ __forceinline__ float blockReduceMax(float v, float* sh) {
    int t = threadIdx.x;
    sh[t] = v; __syncthreads();
    #pragma unroll
    for (int s = 128; s > 0; s >>= 1) { if (t < s) sh[t] = fmaxf(sh[t], sh[t + s]); __syncthreads(); }
    float r = sh[0]; __syncthreads(); return r;
}

__device__ __forceinline__ uint32_t packbf(float lo, float hi) {
    __nv_bfloat162 h = __floats2bfloat162_rn(lo, hi);
    return *(uint32_t*)&h;
}

__device__ __forceinline__ void mma_bf16(float* c, uint32_t a0, uint32_t a1,
                                         uint32_t a2, uint32_t a3,
                                         uint32_t b0, uint32_t b1) {
    asm volatile(
        "mma.sync.aligned.m16n8k16.row.col.f32.bf16.bf16.f32 "
        "{%0,%1,%2,%3}, {%4,%5,%6,%7}, {%8,%9}, {%0,%1,%2,%3};"
        : "+f"(c[0]), "+f"(c[1]), "+f"(c[2]), "+f"(c[3])
        : "r"(a0), "r"(a1), "r"(a2), "r"(a3), "r"(b0), "r"(b1));
}

__device__ __forceinline__ void ldsm_x4(uint32_t& r0, uint32_t& r1, uint32_t& r2,
                                        uint32_t& r3, uint32_t addr) {
    asm volatile("ldmatrix.sync.aligned.m8n8.x4.shared.b16 {%0,%1,%2,%3}, [%4];"
                 : "=r"(r0), "=r"(r1), "=r"(r2), "=r"(r3) : "r"(addr));
}

#define CP_ASYNC16(dst, src) \
    asm volatile("cp.async.cg.shared.global [%0], [%1], 16;" :: "r"(dst), "l"(src))
#define CP_COMMIT asm volatile("cp.async.commit_group;" ::: "memory")
#define CP_WAIT0  asm volatile("cp.async.wait_group 0;" ::: "memory")

// ---------------- bf16 tensor-core GEMM: C = alpha * A @ B^T ----------------
// A: M x K row-major bf16.  B: N x K row-major bf16 (used transposed).
// 128x128 block tile, BK=32, 256 threads (8 warps 4x2), warp tile 32x64.
// cp.async double-buffered smem (2 stages), ldmatrix.x4 fragment loads.
// Smem word tiles [128][20]: STS-vec and LDSM conflict-free.
// CMODE 0: dense.  CMODE 1: causal tile-skip (scores; x=s-tile, y=t-tile).
// CMODE 2: causal K-limit (AV: A rows t only need K <= 128*(y+1) since
//          P[t,s]=0 for s>t — skipped blocks are exact zeros).
// Batched over z: A/C advance by sA/sC; B advances by (z % zmodB)*sB.
#define SW 20
#define TILE_W (128 * SW)
#define STAGE_B (2 * TILE_W * 4)
template <int CMODE, bool OUTBF>
__global__ __launch_bounds__(256)
void bgemm_kernel(const __nv_bfloat16* __restrict__ A, const __nv_bfloat16* __restrict__ Bm,
                  void* __restrict__ Cv, int K, int lda, int ldb, int ldc,
                  long sA, long sB, long sC, int zmodB, float alpha) {
    if (CMODE == 1 && (int)blockIdx.y < (int)blockIdx.x) return;
    A  += (size_t)blockIdx.z * sA;
    Bm += (size_t)(blockIdx.z % zmodB) * sB;

    __shared__ uint32_t sm4[2 * 2 * TILE_W];   // [stage][A|B][128*20] = 40KB

    int tid = threadIdx.x;
    int lane = tid & 31, wid = tid >> 5;
    int gID = lane >> 2, tig = lane & 3;
    int warp_m = (wid & 3) * 32, warp_n = (wid >> 2) * 64;
    int row0 = blockIdx.y * 128, col0 = blockIdx.x * 128;

    uint32_t sbase = (uint32_t)__cvta_generic_to_shared(sm4);

    // loader: each thread moves 2x16B per operand per tile
    int lr = tid >> 1, lh = tid & 1;
    const __nv_bfloat16* Ag = A + (size_t)(row0 + lr) * lda + lh * 16;
    const __nv_bfloat16* Bg = Bm + (size_t)(col0 + lr) * ldb + lh * 16;
    uint32_t adst = sbase + (uint32_t)(lr * SW + lh * 8) * 4;
    uint32_t bdst = adst + TILE_W * 4;

    // ldmatrix lane addressing
    int mat = lane >> 3, mr = lane & 7;
    uint32_t aoff = sbase + (uint32_t)((warp_m + (mat & 1) * 8 + mr) * SW) * 4 + (mat >> 1) * 16;
    uint32_t boff = sbase + TILE_W * 4 +
                    (uint32_t)((warp_n + (mat >> 1) * 8 + mr) * SW) * 4 + (mat & 1) * 16;

    float acc[2][8][4] = {};

    int Keff = K;
    if (CMODE == 2) {
        int klim = ((int)blockIdx.y + 1) * 128;
        Keff = (klim < K) ? klim : K;
    }
    int NT = Keff >> 5;
    // prefetch tile 0 -> stage 0
    CP_ASYNC16(adst, Ag);      CP_ASYNC16(adst + 16, Ag + 8);
    CP_ASYNC16(bdst, Bg);      CP_ASYNC16(bdst + 16, Bg + 8);
    CP_COMMIT;

    for (int t = 0; t < NT; t++) {
        int st = t & 1;
        CP_WAIT0;
        __syncthreads();    // tile t visible to all; all warps done reading stage st^1
        if (t + 1 < NT) {
            int k0 = (t + 1) << 5;
            uint32_t so = (uint32_t)(st ^ 1) * STAGE_B;
            CP_ASYNC16(adst + so, Ag + k0);      CP_ASYNC16(adst + so + 16, Ag + k0 + 8);
            CP_ASYNC16(bdst + so, Bg + k0);      CP_ASYNC16(bdst + so + 16, Bg + k0 + 8);
            CP_COMMIT;
        }
        uint32_t so = (uint32_t)st * STAGE_B;
        #pragma unroll
        for (int s = 0; s < 2; s++) {
            uint32_t a[2][4];
            #pragma unroll
            for (int mt = 0; mt < 2; mt++)
                ldsm_x4(a[mt][0], a[mt][1], a[mt][2], a[mt][3],
                        aoff + so + s * 32 + mt * (16 * SW * 4));
            uint32_t bf[8][2];
            #pragma unroll
            for (int p = 0; p < 4; p++)
                ldsm_x4(bf[2 * p][0], bf[2 * p][1], bf[2 * p + 1][0], bf[2 * p + 1][1],
                        boff + so + s * 32 + p * (16 * SW * 4));
            #pragma unroll
            for (int mt = 0; mt < 2; mt++)
                #pragma unroll
                for (int nt = 0; nt < 8; nt++)
                    mma_bf16(acc[mt][nt], a[mt][0], a[mt][1], a[mt][2], a[mt][3],
                             bf[nt][0], bf[nt][1]);
        }
    }

    if (OUTBF) {
        __nv_bfloat16* C = (__nv_bfloat16*)Cv + (size_t)blockIdx.z * sC;
        #pragma unroll
        for (int mt = 0; mt < 2; mt++) {
            int rg = row0 + warp_m + mt * 16 + gID;
            #pragma unroll
            for (int nt = 0; nt < 8; nt++) {
                int cg = col0 + warp_n + nt * 8 + 2 * tig;
                *(uint32_t*)(C + (size_t)rg * ldc + cg) =
                    packbf(acc[mt][nt][0] * alpha, acc[mt][nt][1] * alpha);
                *(uint32_t*)(C + (size_t)(rg + 8) * ldc + cg) =
                    packbf(acc[mt][nt][2] * alpha, acc[mt][nt][3] * alpha);
            }
        }
    } else {
        float* C = (float*)Cv + (size_t)blockIdx.z * sC;
        #pragma unroll
        for (int mt = 0; mt < 2; mt++) {
            int rg = row0 + warp_m + mt * 16 + gID;
            #pragma unroll
            for (int nt = 0; nt < 8; nt++) {
                int cg = col0 + warp_n + nt * 8 + 2 * tig;
                *(float2*)(C + (size_t)rg * ldc + cg) =
                    make_float2(acc[mt][nt][0] * alpha, acc[mt][nt][1] * alpha);
                *(float2*)(C + (size_t)(rg + 8) * ldc + cg) =
                    make_float2(acc[mt][nt][2] * alpha, acc[mt][nt][3] * alpha);
            }
        }
    }
}

// ---------------- transposes / conversions ----------------
__global__ void transpose_f2b_kernel(const float* __restrict__ in, __nv_bfloat16* __restrict__ out,
                                     int R, int C, long sIn, long sOut) {
    __shared__ float tile[32][33];
    in  += (size_t)blockIdx.z * sIn;
    out += (size_t)blockIdx.z * sOut;
    int c0 = blockIdx.x * 32, r0 = blockIdx.y * 32;
    #pragma unroll
    for (int i = 0; i < 4; i++)
        tile[threadIdx.y + 8 * i][threadIdx.x] =
            in[(size_t)(r0 + threadIdx.y + 8 * i) * C + c0 + threadIdx.x];
    __syncthreads();
    #pragma unroll
    for (int i = 0; i < 4; i++)
        out[(size_t)(c0 + threadIdx.y + 8 * i) * R + r0 + threadIdx.x] =
            __float2bfloat16(tile[threadIdx.x][threadIdx.y + 8 * i]);
}

__global__ void transpose_b2b_kernel(const __nv_bfloat16* __restrict__ in,
                                     __nv_bfloat16* __restrict__ out,
                                     int R, int C, long sIn, long sOut) {
    __shared__ __nv_bfloat16 tile[32][33];
    in  += (size_t)blockIdx.z * sIn;
    out += (size_t)blockIdx.z * sOut;
    int c0 = blockIdx.x * 32, r0 = blockIdx.y * 32;
    #pragma unroll
    for (int i = 0; i < 4; i++)
        tile[threadIdx.y + 8 * i][threadIdx.x] =
            in[(size_t)(r0 + threadIdx.y + 8 * i) * C + c0 + threadIdx.x];
    __syncthreads();
    #pragma unroll
    for (int i = 0; i < 4; i++)
        out[(size_t)(c0 + threadIdx.y + 8 * i) * R + r0 + threadIdx.x] =
            tile[threadIdx.x][threadIdx.y + 8 * i];
}

__global__ void convert_f2b_kernel(const float* __restrict__ in, __nv_bfloat16* __restrict__ out,
                                   int npairs) {
    int i = blockIdx.x * 256 + threadIdx.x;
    if (i < npairs)
        ((__nv_bfloat162*)out)[i] = __floats2bfloat162_rn(in[2 * i], in[2 * i + 1]);
}

// ---------------- LayerNorm (pre): h = LN(x); Z = h (+ bf16 mirrors) ----------------
__global__ void ln_pre_kernel(const float* __restrict__ x, const float* __restrict__ g,
                              const float* __restrict__ b, float* __restrict__ h,
                              float* __restrict__ Z, __nv_bfloat16* __restrict__ hb,
                              __nv_bfloat16* __restrict__ Zb) {
    __shared__ float sh[256];
    int row = blockIdx.x;
    const float* xr = x + (size_t)row * D_;
    float s = 0.f;
    for (int d = threadIdx.x; d < D_; d += 256) s += xr[d];
    float mean = blockReduceSum(s, sh) * (1.0f / D_);
    float v = 0.f;
    for (int d = threadIdx.x; d < D_; d += 256) { float t = xr[d] - mean; v += t * t; }
    float var = blockReduceSum(v, sh) * (1.0f / D_);
    float rstd = rsqrtf(var + 1e-5f);
    for (int d2 = threadIdx.x; d2 < D_ / 2; d2 += 256) {
        int d = 2 * d2;
        float v0 = (xr[d] - mean) * rstd * g[d] + b[d];
        float v1 = (xr[d + 1] - mean) * rstd * g[d + 1] + b[d + 1];
        size_t off = (size_t)row * D_ + d;
        h[off] = v0; h[off + 1] = v1;
        Z[off] = v0; Z[off + 1] = v1;
        __nv_bfloat162 pv = __floats2bfloat162_rn(v0, v1);
        ((__nv_bfloat162*)(hb + off))[0] = pv;
        ((__nv_bfloat162*)(Zb + off))[0] = pv;
    }
}

// ---------------- causal softmax: fp32 scores -> bf16 probs (zero-fill s>t) ----------------
__global__ void softmax_kernel(const float* __restrict__ S, __nv_bfloat16* __restrict__ P) {
    __shared__ float sh[256];
    int row = blockIdx.x;
    int t = row & (T_ - 1);
    const float* r = S + (size_t)row * T_;
    __nv_bfloat16* p = P + (size_t)row * T_;
    float m = -1e30f;
    for (int s = threadIdx.x; s <= t; s += 256) m = fmaxf(m, r[s]);
    m = blockReduceMax(m, sh);
    float sum = 0.f;
    for (int s = threadIdx.x; s <= t; s += 256) sum += __expf(r[s] - m);
    sum = blockReduceSum(sum, sh);
    float inv = 1.f / sum;
    for (int s2 = threadIdx.x; s2 < T_ / 2; s2 += 256) {
        int s = 2 * s2;
        float v0 = (s <= t) ? __expf(r[s] - m) * inv : 0.f;
        float v1 = (s + 1 <= t) ? __expf(r[s + 1] - m) * inv : 0.f;
        ((__nv_bfloat162*)p)[s2] = __floats2bfloat162_rn(v0, v1);
    }
}

// ---------------- parallel-branch epilogue: bf16 delta into concat buffer ----------------
__global__ void finish_par_kernel(const float* __restrict__ h, const float* __restrict__ Eall,
                                  __nv_bfloat16* __restrict__ del, const float* __restrict__ gw,
                                  const float* __restrict__ gb, const float* __restrict__ sp) {
    __shared__ float sh[256];
    int row = blockIdx.x, ci = blockIdx.y;
    const float* zr = h + (size_t)row * D_;
    const float* er = Eall + ((size_t)ci * BT_ + row) * D_;
    float dot = 0.f;
    for (int d = threadIdx.x; d < D_; d += 256) dot += zr[d] * gw[ci * D_ + d];
    dot = blockReduceSum(dot, sh);
    float gate = 1.f / (1.f + __expf(-(dot + gb[ci])));
    float f = log1pf(__expf(sp[ci])) * gate;   // curriculum mask == 1.0f exactly in fp32
    __nv_bfloat16* orow = del + (size_t)row * ND_ + (size_t)ci * D_;
    for (int d2 = threadIdx.x; d2 < D_ / 2; d2 += 256) {
        int d = 2 * d2;
        ((__nv_bfloat162*)orow)[d2] =
            __floats2bfloat162_rn(f * (er[d] - zr[d]), f * (er[d + 1] - zr[d + 1]));
    }
}

// ---------------- sequential-branch epilogue: Z += f*(E - Z) (+ bf16 mirror) ----------------
__global__ void finish_seq_kernel(float* __restrict__ Z, const float* __restrict__ E,
                                  const float* __restrict__ gw, const float* __restrict__ gb,
                                  const float* __restrict__ sp, int ci,
                                  __nv_bfloat16* __restrict__ Zb) {
    __shared__ float sh[256];
    int row = blockIdx.x;
    float* zr = Z + (size_t)row * D_;
    const float* er = E + (size_t)row * D_;
    float dot = 0.f;
    for (int d = threadIdx.x; d < D_; d += 256) dot += zr[d] * gw[ci * D_ + d];
    dot = blockReduceSum(dot, sh);
    float gate = 1.f / (1.f + __expf(-(dot + gb[ci])));
    float f = log1pf(__expf(sp[ci])) * gate;
    __nv_bfloat16* zb = Zb + (size_t)row * D_;
    for (int d2 = threadIdx.x; d2 < D_ / 2; d2 += 256) {
        int d = 2 * d2;
        float z0 = zr[d] + f * (er[d] - zr[d]);
        float z1 = zr[d + 1] + f * (er[d + 1] - zr[d + 1]);
        zr[d] = z0; zr[d + 1] = z1;
        ((__nv_bfloat162*)zb)[d2] = __floats2bfloat162_rn(z0, z1);
    }
}

// ---------------- combine: enr = (1-mg)*(Z-h) + mg*par; LN_post; out = x + rg*enr ----------------
__global__ void combine_kernel(const float* __restrict__ x, const float* __restrict__ h,
                               const float* __restrict__ Z, const float* __restrict__ par,
                               const float* __restrict__ g, const float* __restrict__ b,
                               const float* __restrict__ mode_logit,
                               const float* __restrict__ residual_gate,
                               float* __restrict__ out) {
    __shared__ float sh[256];
    __shared__ float e[D_];
    int row = blockIdx.x;
    float mg = 1.f / (1.f + __expf(-mode_logit[0]));
    float rg = residual_gate[0];
    size_t off = (size_t)row * D_;
    for (int d = threadIdx.x; d < D_; d += 256)
        e[d] = (1.f - mg) * (Z[off + d] - h[off + d]) + mg * par[off + d];
    __syncthreads();
    float s = 0.f;
    for (int d = threadIdx.x; d < D_; d += 256) s += e[d];
    float mean = blockReduceSum(s, sh) * (1.0f / D_);
    float v = 0.f;
    for (int d = threadIdx.x; d < D_; d += 256) { float t = e[d] - mean; v += t * t; }
    float var = blockReduceSum(v, sh) * (1.0f / D_);
    float rstd = rsqrtf(var + 1e-5f);
    for (int d = threadIdx.x; d < D_; d += 256)
        out[off + d] = x[off + d] + rg * ((e[d] - mean) * rstd * g[d] + b[d]);
}

// ---------------- host orchestration ----------------
extern "C" void kernel_launch(void* const* d_in, const int* in_sizes, int n_in,
                              void* d_out, int out_size) {
    (void)in_sizes; (void)n_in; (void)out_size;
    const float* x   = (const float*)d_in[0];
    const float* Wq  = (const float*)d_in[1];
    const float* Wk  = (const float*)d_in[2];
    const float* gw  = (const float*)d_in[3];
    const float* gb  = (const float*)d_in[4];
    const float* sp  = (const float*)d_in[5];
    const float* mW  = (const float*)d_in[6];
    const float* ml  = (const float*)d_in[7];
    const float* rg  = (const float*)d_in[8];
    const float* lpg = (const float*)d_in[9];
    const float* lpb = (const float*)d_in[10];
    const float* lqg = (const float*)d_in[11];
    const float* lqb = (const float*)d_in[12];
    float* out = (float*)d_out;

    float *h, *Z, *S, *E, *par;
    __nv_bfloat16 *hb, *Zb, *hT, *ZT, *WT, *mWb, *qkb, *Pb, *db;
    cudaGetSymbolAddress((void**)&h,   g_h);
    cudaGetSymbolAddress((void**)&Z,   g_Z);
    cudaGetSymbolAddress((void**)&S,   g_S);
    cudaGetSymbolAddress((void**)&E,   g_E);
    cudaGetSymbolAddress((void**)&par, g_par);
    cudaGetSymbolAddress((void**)&hb,  g_hb);
    cudaGetSymbolAddress((void**)&Zb,  g_Zb);
    cudaGetSymbolAddress((void**)&hT,  g_hT);
    cudaGetSymbolAddress((void**)&ZT,  g_ZT);
    cudaGetSymbolAddress((void**)&WT,  g_WT);
    cudaGetSymbolAddress((void**)&mWb, g_mWb);
    cudaGetSymbolAddress((void**)&qkb, g_qkb);
    cudaGetSymbolAddress((void**)&Pb,  g_Pb);
    cudaGetSymbolAddress((void**)&db,  g_db);

    __nv_bfloat16* kb = qkb + (size_t)N_ * BT_ * D_;

    const float alphaS = 1.0f / sqrtf((float)D_);
    const long TD  = (long)T_ * D_;
    const long TT  = (long)T_ * T_;
    const long DT  = (long)D_ * T_;
    const long BTD = (long)BT_ * D_;

    dim3 blk32(32, 8);

    // ---- prologue: LN + bf16 conversions/transposes ----
    ln_pre_kernel<<<BT_, 256>>>(x, lpg, lpb, h, Z, hb, Zb);
    transpose_f2b_kernel<<<dim3(D_ / 32, D_ / 32, N_), blk32>>>(Wq, WT, D_, D_, DD_, DD_);
    transpose_f2b_kernel<<<dim3(D_ / 32, D_ / 32, N_), blk32>>>(
        Wk, WT + (size_t)N_ * DD_, D_, D_, DD_, DD_);
    convert_f2b_kernel<<<((D_ * ND_ / 2) + 255) / 256, 256>>>(mW, mWb, D_ * ND_ / 2);
    transpose_b2b_kernel<<<dim3(D_ / 32, T_ / 32, B_), blk32>>>(hb, hT, T_, D_, TD, DT);
    transpose_b2b_kernel<<<dim3(D_ / 32, T_ / 32, B_), blk32>>>(Zb, ZT, T_, D_, TD, DT);

    // ===== parallel branch: all 7 chambers (q and k fused: z = 0..13) =====
    bgemm_kernel<0, true><<<dim3(6, 32, 2 * N_), 256>>>(
        hb, WT, qkb, D_, D_, D_, D_, 0, (long)DD_, BTD, 2 * N_, 1.f);
    bgemm_kernel<1, false><<<dim3(8, 8, N_ * B_), 256>>>(
        qkb, kb, S, D_, D_, D_, T_, TD, TD, TT, N_ * B_, alphaS);
    softmax_kernel<<<N_ * B_ * T_, 256>>>(S, Pb);
    bgemm_kernel<2, false><<<dim3(6, 8, N_ * B_), 256>>>(
        Pb, hT, E, T_, T_, T_, D_, TT, DT, TD, B_, 1.f);
    finish_par_kernel<<<dim3(BT_, N_), 256>>>(h, E, db, gw, gb, sp);
    bgemm_kernel<0, false><<<dim3(6, 32, 1), 256>>>(
        db, mWb, par, ND_, ND_, ND_, D_, 0, 0, 0, 1, 1.f);

    // ===== sequential branch: dependency chain =====
    for (int i = 0; i < N_; i++) {
        // q and k projections fused: z=0 -> Wq_i -> qkb, z=1 -> Wk_i -> kb
        bgemm_kernel<0, true><<<dim3(6, 32, 2), 256>>>(
            Zb, WT + (size_t)i * DD_, qkb, D_, D_, D_, D_,
            0, (long)N_ * DD_, (long)N_ * BTD, 2, 1.f);
        bgemm_kernel<1, false><<<dim3(8, 8, B_), 256>>>(
            qkb, kb, S, D_, D_, D_, T_, TD, TD, TT, B_, alphaS);
        softmax_kernel<<<BT_, 256>>>(S, Pb);
        bgemm_kernel<2, false><<<dim3(6, 8, B_), 256>>>(
            Pb, ZT, E, T_, T_, T_, D_, TT, DT, TD, B_, 1.f);
        finish_seq_kernel<<<BT_, 256>>>(Z, E, gw, gb, sp, i, Zb);
        transpose_b2b_kernel<<<dim3(D_ / 32, T_ / 32, B_), blk32>>>(Zb, ZT, T_, D_, TD, DT);
    }

    // ===== combine + LN_post + residual =====
    combine_kernel<<<BT_, 256>>>(x, h, Z, par, lqg, lqb, ml, rg, out);
}

// round 16
// speedup vs baseline: 1.2433x; 1.0994x over previous
#include <cuda_runtime.h>
#include <cuda_bf16.h>
#include <cmath>
#include <cstdint>

#define B_ 4
#define T_ 1024
#define D_ 768
#define N_ 7
#define BT_ (B_ * T_)
#define ND_ (N_ * D_)
#define DD_ (D_ * D_)

// ---------------- scratch (device globals; no allocation allowed) ----------------
__device__ float g_h[BT_ * D_];                        // LN(x)  (fp32 master)
__device__ float g_Z[BT_ * D_];                        // h + seq (fp32 master)
__device__ float g_S[(size_t)N_ * B_ * T_ * T_];       // fp32 scores (parallel branch)
__device__ float g_E[(size_t)N_ * BT_ * D_];           // attention outputs (parallel)
__device__ float g_par[BT_ * D_];                      // merged parallel branch

// sequential-chain private scratch (enables concurrent streams)
__device__ float g_Ss[(size_t)B_ * T_ * T_];           // fp32 scores (seq)
__device__ float g_Es[(size_t)BT_ * D_];               // attention outputs (seq)
__device__ __align__(16) __nv_bfloat16 g_qks[(size_t)2 * BT_ * D_]; // [q | k] (seq)
__device__ __align__(16) __nv_bfloat16 g_Ps[(size_t)B_ * T_ * T_];  // probs bf16 (seq)

__device__ __align__(16) __nv_bfloat16 g_hb[BT_ * D_];             // bf16 h
__device__ __align__(16) __nv_bfloat16 g_Zb[BT_ * D_];             // bf16 Z
__device__ __align__(16) __nv_bfloat16 g_hT[(size_t)B_ * D_ * T_]; // h^T per batch
__device__ __align__(16) __nv_bfloat16 g_ZT[(size_t)B_ * D_ * T_]; // Z^T per batch
__device__ __align__(16) __nv_bfloat16 g_WT[(size_t)2 * N_ * DD_]; // [Wq^T(0..6) | Wk^T(0..6)]
__device__ __align__(16) __nv_bfloat16 g_mWb[(size_t)D_ * ND_];    // merge_W bf16
__device__ __align__(16) __nv_bfloat16 g_qkb[(size_t)2 * N_ * BT_ * D_]; // [q(7) | k(7)] (par)
__device__ __align__(16) __nv_bfloat16 g_Pb[(size_t)N_ * B_ * T_ * T_];  // probs bf16 (par)
__device__ __align__(16) __nv_bfloat16 g_db[(size_t)BT_ * ND_];          // deltas bf16

// ---------------- reduction helpers (256 threads) ----------------
__device__ __forceinline__ float blockReduceSum(float v, float* sh) {
    int t = threadIdx.x;
    sh[t] = v; __syncthreads();
    #pragma unroll
    for (int s = 128; s > 0; s >>= 1) { if (t < s) sh[t] += sh[t + s]; __syncthreads(); }
    float r = sh[0]; __syncthreads(); return r;
}
__device__ __forceinline__ float blockReduceMax(float v, float* sh) {
    int t = threadIdx.x;
    sh[t] = v; __syncthreads();
    #pragma unroll
    for (int s = 128; s > 0; s >>= 1) { if (t < s) sh[t] = fmaxf(sh[t], sh[t + s]); __syncthreads(); }
    float r = sh[0]; __syncthreads(); return r;
}

__device__ __forceinline__ uint32_t packbf(float lo, float hi) {
    __nv_bfloat162 h = __floats2bfloat162_rn(lo, hi);
    return *(uint32_t*)&h;
}

__device__ __forceinline__ void mma_bf16(float* c, uint32_t a0, uint32_t a1,
                                         uint32_t a2, uint32_t a3,
                                         uint32_t b0, uint32_t b1) {
    asm volatile(
        "mma.sync.aligned.m16n8k16.row.col.f32.bf16.bf16.f32 "
        "{%0,%1,%2,%3}, {%4,%5,%6,%7}, {%8,%9}, {%0,%1,%2,%3};"
        : "+f"(c[0]), "+f"(c[1]), "+f"(c[2]), "+f"(c[3])
        : "r"(a0), "r"(a1), "r"(a2), "r"(a3), "r"(b0), "r"(b1));
}

__device__ __forceinline__ void ldsm_x4(uint32_t& r0, uint32_t& r1, uint32_t& r2,
                                        uint32_t& r3, uint32_t addr) {
    asm volatile("ldmatrix.sync.aligned.m8n8.x4.shared.b16 {%0,%1,%2,%3}, [%4];"
                 : "=r"(r0), "=r"(r1), "=r"(r2), "=r"(r3) : "r"(addr));
}

#define CP_ASYNC16(dst, src) \
    asm volatile("cp.async.cg.shared.global [%0], [%1], 16;" :: "r"(dst), "l"(src))
#define CP_COMMIT asm volatile("cp.async.commit_group;" ::: "memory")
#define CP_WAIT0  asm volatile("cp.async.wait_group 0;" ::: "memory")

// ---------------- bf16 tensor-core GEMM: C = alpha * A @ B^T ----------------
// A: M x K row-major bf16.  B: N x K row-major bf16 (used transposed).
// 128x128 block tile, BK=32, 256 threads (8 warps 4x2), warp tile 32x64.
// cp.async double-buffered smem (2 stages), ldmatrix.x4 fragment loads.
// Smem word tiles [128][20]: STS-vec and LDSM conflict-free.
// CMODE 0: dense.  CMODE 1: causal tile-skip (scores; x=s-tile, y=t-tile).
// CMODE 2: causal K-limit (AV: A rows t only need K <= 128*(y+1) since
//          P[t,s]=0 for s>t — skipped blocks are exact zeros).
// Batched over z: A/C advance by sA/sC; B advances by (z % zmodB)*sB.
#define SW 20
#define TILE_W (128 * SW)
#define STAGE_B (2 * TILE_W * 4)
template <int CMODE, bool OUTBF>
__global__ __launch_bounds__(256)
void bgemm_kernel(const __nv_bfloat16* __restrict__ A, const __nv_bfloat16* __restrict__ Bm,
                  void* __restrict__ Cv, int K, int lda, int ldb, int ldc,
                  long sA, long sB, long sC, int zmodB, float alpha) {
    if (CMODE == 1 && (int)blockIdx.y < (int)blockIdx.x) return;
    A  += (size_t)blockIdx.z * sA;
    Bm += (size_t)(blockIdx.z % zmodB) * sB;

    __shared__ uint32_t sm4[2 * 2 * TILE_W];   // [stage][A|B][128*20] = 40KB

    int tid = threadIdx.x;
    int lane = tid & 31, wid = tid >> 5;
    int gID = lane >> 2, tig = lane & 3;
    int warp_m = (wid & 3) * 32, warp_n = (wid >> 2) * 64;
    int row0 = blockIdx.y * 128, col0 = blockIdx.x * 128;

    uint32_t sbase = (uint32_t)__cvta_generic_to_shared(sm4);

    // loader: each thread moves 2x16B per operand per tile
    int lr = tid >> 1, lh = tid & 1;
    const __nv_bfloat16* Ag = A + (size_t)(row0 + lr) * lda + lh * 16;
    const __nv_bfloat16* Bg = Bm + (size_t)(col0 + lr) * ldb + lh * 16;
    uint32_t adst = sbase + (uint32_t)(lr * SW + lh * 8) * 4;
    uint32_t bdst = adst + TILE_W * 4;

    // ldmatrix lane addressing
    int mat = lane >> 3, mr = lane & 7;
    uint32_t aoff = sbase + (uint32_t)((warp_m + (mat & 1) * 8 + mr) * SW) * 4 + (mat >> 1) * 16;
    uint32_t boff = sbase + TILE_W * 4 +
                    (uint32_t)((warp_n + (mat >> 1) * 8 + mr) * SW) * 4 + (mat & 1) * 16;

    float acc[2][8][4] = {};

    int Keff = K;
    if (CMODE == 2) {
        int klim = ((int)blockIdx.y + 1) * 128;
        Keff = (klim < K) ? klim : K;
    }
    int NT = Keff >> 5;
    // prefetch tile 0 -> stage 0
    CP_ASYNC16(adst, Ag);      CP_ASYNC16(adst + 16, Ag + 8);
    CP_ASYNC16(bdst, Bg);      CP_ASYNC16(bdst + 16, Bg + 8);
    CP_COMMIT;

    for (int t = 0; t < NT; t++) {
        int st = t & 1;
        CP_WAIT0;
        __syncthreads();    // tile t visible to all; all warps done reading stage st^1
        if (t + 1 < NT) {
            int k0 = (t + 1) << 5;
            uint32_t so = (uint32_t)(st ^ 1) * STAGE_B;
            CP_ASYNC16(adst + so, Ag + k0);      CP_ASYNC16(adst + so + 16, Ag + k0 + 8);
            CP_ASYNC16(bdst + so, Bg + k0);      CP_ASYNC16(bdst + so + 16, Bg + k0 + 8);
            CP_COMMIT;
        }
        uint32_t so = (uint32_t)st * STAGE_B;
        #pragma unroll
        for (int s = 0; s < 2; s++) {
            uint32_t a[2][4];
            #pragma unroll
            for (int mt = 0; mt < 2; mt++)
                ldsm_x4(a[mt][0], a[mt][1], a[mt][2], a[mt][3],
                        aoff + so + s * 32 + mt * (16 * SW * 4));
            uint32_t bf[8][2];
            #pragma unroll
            for (int p = 0; p < 4; p++)
                ldsm_x4(bf[2 * p][0], bf[2 * p][1], bf[2 * p + 1][0], bf[2 * p + 1][1],
                        boff + so + s * 32 + p * (16 * SW * 4));
            #pragma unroll
            for (int mt = 0; mt < 2; mt++)
                #pragma unroll
                for (int nt = 0; nt < 8; nt++)
                    mma_bf16(acc[mt][nt], a[mt][0], a[mt][1], a[mt][2], a[mt][3],
                             bf[nt][0], bf[nt][1]);
        }
    }

    if (OUTBF) {
        __nv_bfloat16* C = (__nv_bfloat16*)Cv + (size_t)blockIdx.z * sC;
        #pragma unroll
        for (int mt = 0; mt < 2; mt++) {
            int rg = row0 + warp_m + mt * 16 + gID;
            #pragma unroll
            for (int nt = 0; nt < 8; nt++) {
                int cg = col0 + warp_n + nt * 8 + 2 * tig;
                *(uint32_t*)(C + (size_t)rg * ldc + cg) =
                    packbf(acc[mt][nt][0] * alpha, acc[mt][nt][1] * alpha);
                *(uint32_t*)(C + (size_t)(rg + 8) * ldc + cg) =
                    packbf(acc[mt][nt][2] * alpha, acc[mt][nt][3] * alpha);
            }
        }
    } else {
        float* C = (float*)Cv + (size_t)blockIdx.z * sC;
        #pragma unroll
        for (int mt = 0; mt < 2; mt++) {
            int rg = row0 + warp_m + mt * 16 + gID;
            #pragma unroll
            for (int nt = 0; nt < 8; nt++) {
                int cg = col0 + warp_n + nt * 8 + 2 * tig;
                *(float2*)(C + (size_t)rg * ldc + cg) =
                    make_float2(acc[mt][nt][0] * alpha, acc[mt][nt][1] * alpha);
                *(float2*)(C + (size_t)(rg + 8) * ldc + cg) =
                    make_float2(acc[mt][nt][2] * alpha, acc[mt][nt][3] * alpha);
            }
        }
    }
}

// ---------------- transposes / conversions ----------------
__global__ void transpose_f2b_kernel(const float* __restrict__ in, __nv_bfloat16* __restrict__ out,
                                     int R, int C, long sIn, long sOut) {
    __shared__ float tile[32][33];
    in  += (size_t)blockIdx.z * sIn;
    out += (size_t)blockIdx.z * sOut;
    int c0 = blockIdx.x * 32, r0 = blockIdx.y * 32;
    #pragma unroll
    for (int i = 0; i < 4; i++)
        tile[threadIdx.y + 8 * i][threadIdx.x] =
            in[(size_t)(r0 + threadIdx.y + 8 * i) * C + c0 + threadIdx.x];
    __syncthreads();
    #pragma unroll
    for (int i = 0; i < 4; i++)
        out[(size_t)(c0 + threadIdx.y + 8 * i) * R + r0 + threadIdx.x] =
            __float2bfloat16(tile[threadIdx.x][threadIdx.y + 8 * i]);
}

__global__ void transpose_b2b_kernel(const __nv_bfloat16* __restrict__ in,
                                     __nv_bfloat16* __restrict__ out,
                                     int R, int C, long sIn, long sOut) {
    __shared__ __nv_bfloat16 tile[32][33];
    in  += (size_t)blockIdx.z * sIn;
    out += (size_t)blockIdx.z * sOut;
    int c0 = blockIdx.x * 32, r0 = blockIdx.y * 32;
    #pragma unroll
    for (int i = 0; i < 4; i++)
        tile[threadIdx.y + 8 * i][threadIdx.x] =
            in[(size_t)(r0 + threadIdx.y + 8 * i) * C + c0 + threadIdx.x];
    __syncthreads();
    #pragma unroll
    for (int i = 0; i < 4; i++)
        out[(size_t)(c0 + threadIdx.y + 8 * i) * R + r0 + threadIdx.x] =
            tile[threadIdx.x][threadIdx.y + 8 * i];
}

__global__ void convert_f2b_kernel(const float* __restrict__ in, __nv_bfloat16* __restrict__ out,
                                   int npairs) {
    int i = blockIdx.x * 256 + threadIdx.x;
    if (i < npairs)
        ((__nv_bfloat162*)out)[i] = __floats2bfloat162_rn(in[2 * i], in[2 * i + 1]);
}

// ---------------- LayerNorm (pre): h = LN(x); Z = h (+ bf16 mirrors) ----------------
__global__ void ln_pre_kernel(const float* __restrict__ x, const float* __restrict__ g,
                              const float* __restrict__ b, float* __restrict__ h,
                              float* __restrict__ Z, __nv_bfloat16* __restrict__ hb,
                              __nv_bfloat16* __restrict__ Zb) {
    __shared__ float sh[256];
    int row = blockIdx.x;
    const float* xr = x + (size_t)row * D_;
    float s = 0.f;
    for (int d = threadIdx.x; d < D_; d += 256) s += xr[d];
    float mean = blockReduceSum(s, sh) * (1.0f / D_);
    float v = 0.f;
    for (int d = threadIdx.x; d < D_; d += 256) { float t = xr[d] - mean; v += t * t; }
    float var = blockReduceSum(v, sh) * (1.0f / D_);
    float rstd = rsqrtf(var + 1e-5f);
    for (int d2 = threadIdx.x; d2 < D_ / 2; d2 += 256) {
        int d = 2 * d2;
        float v0 = (xr[d] - mean) * rstd * g[d] + b[d];
        float v1 = (xr[d + 1] - mean) * rstd * g[d + 1] + b[d + 1];
        size_t off = (size_t)row * D_ + d;
        h[off] = v0; h[off + 1] = v1;
        Z[off] = v0; Z[off + 1] = v1;
        __nv_bfloat162 pv = __floats2bfloat162_rn(v0, v1);
        ((__nv_bfloat162*)(hb + off))[0] = pv;
        ((__nv_bfloat162*)(Zb + off))[0] = pv;
    }
}

// ---------------- causal softmax: fp32 scores -> bf16 probs (zero-fill s>t) ----------------
__global__ void softmax_kernel(const float* __restrict__ S, __nv_bfloat16* __restrict__ P) {
    __shared__ float sh[256];
    int row = blockIdx.x;
    int t = row & (T_ - 1);
    const float* r = S + (size_t)row * T_;
    __nv_bfloat16* p = P + (size_t)row * T_;
    float m = -1e30f;
    for (int s = threadIdx.x; s <= t; s += 256) m = fmaxf(m, r[s]);
    m = blockReduceMax(m, sh);
    float sum = 0.f;
    for (int s = threadIdx.x; s <= t; s += 256) sum += __expf(r[s] - m);
    sum = blockReduceSum(sum, sh);
    float inv = 1.f / sum;
    for (int s2 = threadIdx.x; s2 < T_ / 2; s2 += 256) {
        int s = 2 * s2;
        float v0 = (s <= t) ? __expf(r[s] - m) * inv : 0.f;
        float v1 = (s + 1 <= t) ? __expf(r[s + 1] - m) * inv : 0.f;
        ((__nv_bfloat162*)p)[s2] = __floats2bfloat162_rn(v0, v1);
    }
}

// ---------------- parallel-branch epilogue: bf16 delta into concat buffer ----------------
__global__ void finish_par_kernel(const float* __restrict__ h, const float* __restrict__ Eall,
                                  __nv_bfloat16* __restrict__ del, const float* __restrict__ gw,
                                  const float* __restrict__ gb, const float* __restrict__ sp) {
    __shared__ float sh[256];
    int row = blockIdx.x, ci = blockIdx.y;
    const float* zr = h + (size_t)row * D_;
    const float* er = Eall + ((size_t)ci * BT_ + row) * D_;
    float dot = 0.f;
    for (int d = threadIdx.x; d < D_; d += 256) dot += zr[d] * gw[ci * D_ + d];
    dot = blockReduceSum(dot, sh);
    float gate = 1.f / (1.f + __expf(-(dot + gb[ci])));
    float f = log1pf(__expf(sp[ci])) * gate;   // curriculum mask == 1.0f exactly in fp32
    __nv_bfloat16* orow = del + (size_t)row * ND_ + (size_t)ci * D_;
    for (int d2 = threadIdx.x; d2 < D_ / 2; d2 += 256) {
        int d = 2 * d2;
        ((__nv_bfloat162*)orow)[d2] =
            __floats2bfloat162_rn(f * (er[d] - zr[d]), f * (er[d + 1] - zr[d + 1]));
    }
}

// ---------------- sequential-branch epilogue: Z += f*(E - Z) (+ bf16 mirror) ----------------
__global__ void finish_seq_kernel(float* __restrict__ Z, const float* __restrict__ E,
                                  const float* __restrict__ gw, const float* __restrict__ gb,
                                  const float* __restrict__ sp, int ci,
                                  __nv_bfloat16* __restrict__ Zb) {
    __shared__ float sh[256];
    int row = blockIdx.x;
    float* zr = Z + (size_t)row * D_;
    const float* er = E + (size_t)row * D_;
    float dot = 0.f;
    for (int d = threadIdx.x; d < D_; d += 256) dot += zr[d] * gw[ci * D_ + d];
    dot = blockReduceSum(dot, sh);
    float gate = 1.f / (1.f + __expf(-(dot + gb[ci])));
    float f = log1pf(__expf(sp[ci])) * gate;
    __nv_bfloat16* zb = Zb + (size_t)row * D_;
    for (int d2 = threadIdx.x; d2 < D_ / 2; d2 += 256) {
        int d = 2 * d2;
        float z0 = zr[d] + f * (er[d] - zr[d]);
        float z1 = zr[d + 1] + f * (er[d + 1] - zr[d + 1]);
        zr[d] = z0; zr[d + 1] = z1;
        ((__nv_bfloat162*)zb)[d2] = __floats2bfloat162_rn(z0, z1);
    }
}

// ---------------- combine: enr = (1-mg)*(Z-h) + mg*par; LN_post; out = x + rg*enr ----------------
__global__ void combine_kernel(const float* __restrict__ x, const float* __restrict__ h,
                               const float* __restrict__ Z, const float* __restrict__ par,
                               const float* __restrict__ g, const float* __restrict__ b,
                               const float* __restrict__ mode_logit,
                               const float* __restrict__ residual_gate,
                               float* __restrict__ out) {
    __shared__ float sh[256];
    __shared__ float e[D_];
    int row = blockIdx.x;
    float mg = 1.f / (1.f + __expf(-mode_logit[0]));
    float rg = residual_gate[0];
    size_t off = (size_t)row * D_;
    for (int d = threadIdx.x; d < D_; d += 256)
        e[d] = (1.f - mg) * (Z[off + d] - h[off + d]) + mg * par[off + d];
    __syncthreads();
    float s = 0.f;
    for (int d = threadIdx.x; d < D_; d += 256) s += e[d];
    float mean = blockReduceSum(s, sh) * (1.0f / D_);
    float v = 0.f;
    for (int d = threadIdx.x; d < D_; d += 256) { float t = e[d] - mean; v += t * t; }
    float var = blockReduceSum(v, sh) * (1.0f / D_);
    float rstd = rsqrtf(var + 1e-5f);
    for (int d = threadIdx.x; d < D_; d += 256)
        out[off + d] = x[off + d] + rg * ((e[d] - mean) * rstd * g[d] + b[d]);
}

// ---------------- host orchestration ----------------
extern "C" void kernel_launch(void* const* d_in, const int* in_sizes, int n_in,
                              void* d_out, int out_size) {
    (void)in_sizes; (void)n_in; (void)out_size;
    const float* x   = (const float*)d_in[0];
    const float* Wq  = (const float*)d_in[1];
    const float* Wk  = (const float*)d_in[2];
    const float* gw  = (const float*)d_in[3];
    const float* gb  = (const float*)d_in[4];
    const float* sp  = (const float*)d_in[5];
    const float* mW  = (const float*)d_in[6];
    const float* ml  = (const float*)d_in[7];
    const float* rg  = (const float*)d_in[8];
    const float* lpg = (const float*)d_in[9];
    const float* lpb = (const float*)d_in[10];
    const float* lqg = (const float*)d_in[11];
    const float* lqb = (const float*)d_in[12];
    float* out = (float*)d_out;

    float *h, *Z, *S, *E, *par, *Ss, *Es;
    __nv_bfloat16 *hb, *Zb, *hT, *ZT, *WT, *mWb, *qkb, *Pb, *db, *qks, *Ps;
    cudaGetSymbolAddress((void**)&h,   g_h);
    cudaGetSymbolAddress((void**)&Z,   g_Z);
    cudaGetSymbolAddress((void**)&S,   g_S);
    cudaGetSymbolAddress((void**)&E,   g_E);
    cudaGetSymbolAddress((void**)&par, g_par);
    cudaGetSymbolAddress((void**)&Ss,  g_Ss);
    cudaGetSymbolAddress((void**)&Es,  g_Es);
    cudaGetSymbolAddress((void**)&hb,  g_hb);
    cudaGetSymbolAddress((void**)&Zb,  g_Zb);
    cudaGetSymbolAddress((void**)&hT,  g_hT);
    cudaGetSymbolAddress((void**)&ZT,  g_ZT);
    cudaGetSymbolAddress((void**)&WT,  g_WT);
    cudaGetSymbolAddress((void**)&mWb, g_mWb);
    cudaGetSymbolAddress((void**)&qkb, g_qkb);
    cudaGetSymbolAddress((void**)&Pb,  g_Pb);
    cudaGetSymbolAddress((void**)&db,  g_db);
    cudaGetSymbolAddress((void**)&qks, g_qks);
    cudaGetSymbolAddress((void**)&Ps,  g_Ps);

    __nv_bfloat16* kb = qkb + (size_t)N_ * BT_ * D_;
    __nv_bfloat16* ks = qks + (size_t)BT_ * D_;

    // one-time host objects (host-side only; device work stays identical per call)
    static cudaStream_t s2 = nullptr;
    static cudaEvent_t evFork = nullptr, evJoin = nullptr;
    if (s2 == nullptr) {
        cudaStreamCreateWithFlags(&s2, cudaStreamNonBlocking);
        cudaEventCreateWithFlags(&evFork, cudaEventDisableTiming);
        cudaEventCreateWithFlags(&evJoin, cudaEventDisableTiming);
    }

    const float alphaS = 1.0f / sqrtf((float)D_);
    const long TD  = (long)T_ * D_;
    const long TT  = (long)T_ * T_;
    const long DT  = (long)D_ * T_;
    const long BTD = (long)BT_ * D_;

    dim3 blk32(32, 8);

    // ---- prologue (stream 0): LN + bf16 conversions/transposes ----
    ln_pre_kernel<<<BT_, 256>>>(x, lpg, lpb, h, Z, hb, Zb);
    transpose_f2b_kernel<<<dim3(D_ / 32, D_ / 32, N_), blk32>>>(Wq, WT, D_, D_, DD_, DD_);
    transpose_f2b_kernel<<<dim3(D_ / 32, D_ / 32, N_), blk32>>>(
        Wk, WT + (size_t)N_ * DD_, D_, D_, DD_, DD_);
    convert_f2b_kernel<<<((D_ * ND_ / 2) + 255) / 256, 256>>>(mW, mWb, D_ * ND_ / 2);
    transpose_b2b_kernel<<<dim3(D_ / 32, T_ / 32, B_), blk32>>>(hb, hT, T_, D_, TD, DT);
    transpose_b2b_kernel<<<dim3(D_ / 32, T_ / 32, B_), blk32>>>(Zb, ZT, T_, D_, TD, DT);

    // ---- fork: parallel branch runs on s2 concurrently with the sequential chain ----
    cudaEventRecord(evFork, 0);
    cudaStreamWaitEvent(s2, evFork, 0);

    // ===== parallel branch (stream s2): all 7 chambers (q and k fused: z = 0..13) =====
    bgemm_kernel<0, true><<<dim3(6, 32, 2 * N_), 256, 0, s2>>>(
        hb, WT, qkb, D_, D_, D_, D_, 0, (long)DD_, BTD, 2 * N_, 1.f);
    bgemm_kernel<1, false><<<dim3(8, 8, N_ * B_), 256, 0, s2>>>(
        qkb, kb, S, D_, D_, D_, T_, TD, TD, TT, N_ * B_, alphaS);
    softmax_kernel<<<N_ * B_ * T_, 256, 0, s2>>>(S, Pb);
    bgemm_kernel<2, false><<<dim3(6, 8, N_ * B_), 256, 0, s2>>>(
        Pb, hT, E, T_, T_, T_, D_, TT, DT, TD, B_, 1.f);
    finish_par_kernel<<<dim3(BT_, N_), 256, 0, s2>>>(h, E, db, gw, gb, sp);
    bgemm_kernel<0, false><<<dim3(6, 32, 1), 256, 0, s2>>>(
        db, mWb, par, ND_, ND_, ND_, D_, 0, 0, 0, 1, 1.f);
    cudaEventRecord(evJoin, s2);

    // ===== sequential branch (stream 0): dependency chain, private scratch =====
    for (int i = 0; i < N_; i++) {
        // q and k projections fused: z=0 -> Wq_i -> qks, z=1 -> Wk_i -> ks
        bgemm_kernel<0, true><<<dim3(6, 32, 2), 256>>>(
            Zb, WT + (size_t)i * DD_, qks, D_, D_, D_, D_,
            0, (long)N_ * DD_, BTD, 2, 1.f);
        bgemm_kernel<1, false><<<dim3(8, 8, B_), 256>>>(
            qks, ks, Ss, D_, D_, D_, T_, TD, TD, TT, B_, alphaS);
        softmax_kernel<<<BT_, 256>>>(Ss, Ps);
        bgemm_kernel<2, false><<<dim3(6, 8, B_), 256>>>(
            Ps, ZT, Es, T_, T_, T_, D_, TT, DT, TD, B_, 1.f);
        finish_seq_kernel<<<BT_, 256>>>(Z, Es, gw, gb, sp, i, Zb);
        transpose_b2b_kernel<<<dim3(D_ / 32, T_ / 32, B_), blk32>>>(Zb, ZT, T_, D_, TD, DT);
    }

    // ---- join: combine needs both Z (stream 0) and par (s2) ----
    cudaStreamWaitEvent(0, evJoin, 0);

    // ===== combine + LN_post + residual =====
    combine_kernel<<<BT_, 256>>>(x, h, Z, par, lqg, lqb, ml, rg, out);
}